// round 16
// baseline (speedup 1.0000x reference)
#include <cuda_runtime.h>
#include <cuda_fp16.h>

#define NTHR   512
#define BT     16
#define HDIM   256
#define EDIM   32
#define TSTEPS 64
#define G3     768
#define KB     8
#define NKT    18
#define NNT    96

#define HS_STR 260
#define A_PITCH 296            // fp16 elems per A row
#define A_U32   148            // u32 per A row
#define A_PLANE 2368           // u32 per A plane (16 rows)
#define PSTR    20

// smem offsets (floats)
#define OFF_AH    0            // 2 planes x 2368 = 4736
#define OFF_HS    4736         // 16*260 = 4160
#define ENC_WS    8896         // 2080
#define ENC_XA    10976        // 4160
#define OFF_BSUM  15136        // 768
#define OFF_BHH   15904        // 768
#define OFF_BIH   16672        // 768
#define OFF_WH    17440        // 256
#define OFF_WB    17696        // 32
#define OFF_PART  17728        // 16*20 = 320
#define OFF_BE1   18048        // 256
#define OFF_BE2   18304        // 256
#define SMEM_FLOATS 18560
#define SMEM_BYTES  (SMEM_FLOATS * 4)   // 74240 bytes (2 CTAs/SM fit)

// fp16 W fragments: per (tk,tn,lane): {b0,b1} fp16x2
__device__ uint2 g_wfrag[NKT * NNT * 32];

__device__ __forceinline__ unsigned long long pack2(float x) {
    unsigned long long r; asm("mov.b64 %0, {%1,%1};" : "=l"(r) : "f"(x)); return r;
}
__device__ __forceinline__ void fma2(unsigned long long& d, unsigned long long a, unsigned long long b) {
    asm("fma.rn.f32x2 %0, %1, %2, %0;" : "+l"(d) : "l"(a), "l"(b));
}
__device__ __forceinline__ float2 up2(unsigned long long v) {
    float2 f; asm("mov.b64 {%0,%1}, %2;" : "=f"(f.x), "=f"(f.y) : "l"(v)); return f;
}
__device__ __forceinline__ float sigf(float x)  { return 1.0f / (1.0f + __expf(-x)); }
__device__ __forceinline__ float tanhff(float x){ return 1.0f - 2.0f / (__expf(2.0f * x) + 1.0f); }

__device__ __forceinline__ void mma_f16(float* c, const unsigned* a, unsigned b0, unsigned b1) {
    asm("mma.sync.aligned.m16n8k16.row.col.f32.f16.f16.f32 "
        "{%0,%1,%2,%3},{%4,%5,%6,%7},{%8,%9},{%0,%1,%2,%3};"
        : "+f"(c[0]), "+f"(c[1]), "+f"(c[2]), "+f"(c[3])
        : "r"(a[0]), "r"(a[1]), "r"(a[2]), "r"(a[3]), "r"(b0), "r"(b1));
}
__device__ __forceinline__ void ldmat_x4(unsigned* r, unsigned addr) {
    asm volatile("ldmatrix.sync.aligned.m8n8.x4.shared.b16 {%0,%1,%2,%3}, [%4];"
        : "=r"(r[0]), "=r"(r[1]), "=r"(r[2]), "=r"(r[3]) : "r"(addr));
}
__device__ __forceinline__ unsigned packh2(__half a, __half b) {
    return (unsigned)__half_as_ushort(a) | ((unsigned)__half_as_ushort(b) << 16);
}
__device__ __forceinline__ unsigned cvt2h(float a, float b) {
    return packh2(__float2half_rn(a), __float2half_rn(b));
}

// ---------- prep: fp16 B-fragments of Wcat = [Whh | Wih] ----------
__global__ void prep_kernel(const float* __restrict__ Whh, const float* __restrict__ Wih) {
    int idx = blockIdx.x * blockDim.x + threadIdx.x;
    if (idx >= NKT * NNT * 32) return;
    int l    = idx & 31;
    int tile = idx >> 5;
    int tn   = tile % NNT;
    int tk   = tile / NNT;
    int n    = tn * 8 + (l >> 2);
    int kb   = tk * 16 + (l & 3) * 2;

    float v[4];
    #pragma unroll
    for (int q = 0; q < 4; q++) {
        int k = kb + (q & 1) + (q >> 1) * 8;
        v[q] = (k < HDIM) ? Whh[n * HDIM + k] : Wih[n * EDIM + (k - HDIM)];
    }
    uint2 o;
    o.x = cvt2h(v[0], v[1]);
    o.y = cvt2h(v[2], v[3]);
    g_wfrag[idx] = o;
}

// ---------- encoder stage (fp32, runs once; 512 threads, 16 rows) ----------
__device__ __forceinline__ void encoder_stage(
    const float* __restrict__ in, int instr,
    const float* __restrict__ Wg, const float* __restrict__ bias_s,
    float* __restrict__ outp, float* __restrict__ ws)
{
    const int tid = threadIdx.x;
    const int c0 = (tid & 63) * 4;
    const int r0 = (tid >> 6) * 2;
    unsigned long long acc[2][2];
    {
        unsigned long long bp0 = *(const unsigned long long*)(bias_s + c0);
        unsigned long long bp1 = *(const unsigned long long*)(bias_s + c0 + 2);
        #pragma unroll
        for (int r = 0; r < 2; r++) { acc[r][0] = bp0; acc[r][1] = bp1; }
    }
    for (int kc = 0; kc < HDIM / KB; kc++) {
        __syncthreads();
        for (int i = tid; i < KB * HDIM; i += NTHR) {
            int j = i >> 3, k = i & 7;
            ws[k * 260 + j] = Wg[j * HDIM + kc * KB + k];
        }
        __syncthreads();
        #pragma unroll
        for (int k = 0; k < KB; k++) {
            ulonglong2 w = *(const ulonglong2*)(ws + k * 260 + c0);
            #pragma unroll
            for (int r = 0; r < 2; r++) {
                unsigned long long a = pack2(in[(r0 + r) * instr + kc * KB + k]);
                fma2(acc[r][0], a, w.x);
                fma2(acc[r][1], a, w.y);
            }
        }
    }
    __syncthreads();
    #pragma unroll
    for (int r = 0; r < 2; r++) {
        float2 v0 = up2(acc[r][0]);
        float2 v1 = up2(acc[r][1]);
        float* o = outp + (r0 + r) * HS_STR + c0;
        o[0] = fmaxf(v0.x, 0.f); o[1] = fmaxf(v0.y, 0.f);
        o[2] = fmaxf(v1.x, 0.f); o[3] = fmaxf(v1.y, 0.f);
    }
}

extern __shared__ float smem[];

__global__ void __launch_bounds__(NTHR, 2)
gru_kernel(const float* __restrict__ x,   const int*   __restrict__ targets,
           const float* __restrict__ We1, const float* __restrict__ be1,
           const float* __restrict__ We2, const float* __restrict__ be2,
           const float* __restrict__ Wih, const float* __restrict__ bih,
           const float* __restrict__ Whh, const float* __restrict__ bhh,
           const float* __restrict__ Wdec,const float* __restrict__ bdec,
           float* __restrict__ out)
{
    unsigned* Ah32 = (unsigned*)(smem + OFF_AH);
    float* hs     = smem + OFF_HS;
    float* bsum_s = smem + OFF_BSUM;
    float* bhh_s  = smem + OFF_BHH;
    float* bih_s  = smem + OFF_BIH;
    float* wh_s   = smem + OFF_WH;
    float* wb_s   = smem + OFF_WB;
    float* part   = smem + OFF_PART;
    float* be1_s  = smem + OFF_BE1;
    float* be2_s  = smem + OFF_BE2;

    const int tid  = threadIdx.x;
    const int row0 = blockIdx.x * BT;
    const int u    = tid >> 5;       // warp 0..15
    const int lane = tid & 31;

    for (int i = tid; i < G3; i += NTHR) {
        float a = bhh[i], b = bih[i];
        bhh_s[i] = a; bih_s[i] = b; bsum_s[i] = a + b;
    }
    for (int i = tid; i < HDIM; i += NTHR) {
        wh_s[i] = Wdec[i]; be1_s[i] = be1[i]; be2_s[i] = be2[i];
    }
    if (tid < EDIM) wb_s[tid] = Wdec[HDIM + tid];
    const float b0 = bdec[0];

    // encoder: x -> xa -> hs (16 rows)
    {
        float* ws = smem + ENC_WS;
        float* xa = smem + ENC_XA;
        for (int i = tid; i < BT * HDIM; i += NTHR) {
            int r = i >> 8, c = i & 255;
            xa[r * 260 + c] = x[(row0 + r) * HDIM + c];
        }
        __syncthreads();
        encoder_stage(xa, 260, We1, be1_s, hs, ws);
        encoder_stage(hs, HS_STR, We2, be2_s, hs, ws);
        __syncthreads();
    }

    // initial A plane 0: h0 fp16, prev = 0, pads = 0
    for (int i = tid; i < BT * A_U32; i += NTHR) {
        int r = i / A_U32, cu = i - r * A_U32;
        unsigned hi = 0;
        if (cu < 128) hi = cvt2h(hs[r * HS_STR + 2 * cu], hs[r * HS_STR + 2 * cu + 1]);
        Ah32[r * A_U32 + cu] = hi;
    }
    __syncthreads();

    const int l4 = lane >> 2;
    const int l2 = (lane & 3) * 2;
    const unsigned aoff = (unsigned)((lane & 15) * A_PITCH + (lane >> 4) * 8) * 2u;
    const unsigned ahi_base0 = (unsigned)__cvta_generic_to_shared(Ah32) + aoff;

    const int out_base = (row0 + u) * TSTEPS * EDIM + lane;

    for (int t = 0; t < TSTEPS; t++) {
        const unsigned ahr = ahi_base0 + (unsigned)(t & 1) * (A_PLANE * 4u);
        unsigned* AhW = Ah32 + ((t + 1) & 1) * A_PLANE;

        const int idx = out_base + t * EDIM;
        const int tgt = targets[idx];

        // ===== GEMM: gates[16 x 768] = [h|prev] @ Wcat^T + biases =====
        // warp u owns n-tiles {u+16j+32i : j<2, i<3}; single m-tile (M=16)
        float acc[3][2][4];
        float accg[2][4];
        {
            #pragma unroll
            for (int i = 0; i < 3; i++)
                #pragma unroll
                for (int j = 0; j < 2; j++) {
                    int n0 = (u + 16 * j + 32 * i) * 8 + l2;
                    float v0 = (i < 2) ? bsum_s[n0]     : bhh_s[n0];
                    float v1 = (i < 2) ? bsum_s[n0 + 1] : bhh_s[n0 + 1];
                    acc[i][j][0] = v0; acc[i][j][1] = v1;
                    acc[i][j][2] = v0; acc[i][j][3] = v1;
                }
            #pragma unroll
            for (int j = 0; j < 2; j++) {
                int n0 = (u + 16 * j + 64) * 8 + l2;
                float v0 = bih_s[n0], v1 = bih_s[n0 + 1];
                accg[j][0] = v0; accg[j][1] = v1;
                accg[j][2] = v0; accg[j][3] = v1;
            }
            #pragma unroll 3
            for (int tk = 0; tk < 16; tk++) {
                unsigned ah[4];
                ldmat_x4(ah, ahr + (unsigned)(tk * 32));
                #pragma unroll
                for (int i = 0; i < 3; i++)
                    #pragma unroll
                    for (int j = 0; j < 2; j++) {
                        uint2 b = g_wfrag[(tk * NNT + u + 16 * j + 32 * i) * 32 + lane];
                        mma_f16(acc[i][j], ah, b.x, b.y);
                    }
            }
            #pragma unroll
            for (int tt = 0; tt < 2; tt++) {
                int tk = 16 + tt;
                unsigned ah[4];
                ldmat_x4(ah, ahr + (unsigned)(tk * 32));
                #pragma unroll
                for (int i = 0; i < 3; i++)
                    #pragma unroll
                    for (int j = 0; j < 2; j++) {
                        uint2 b = g_wfrag[(tk * NNT + u + 16 * j + 32 * i) * 32 + lane];
                        float* T = (i < 2) ? acc[i][j] : accg[j];
                        mma_f16(T, ah, b.x, b.y);
                    }
            }
        }
        // no barrier: phase 2 writes the other A plane; hs cols are warp-private

        // ===== phase 2: gates, h update (smem), A-plane write, psum =====
        {
            float ps[2] = {0.f, 0.f};
            #pragma unroll
            for (int j = 0; j < 2; j++) {
                int cbase = 8 * u + 128 * j + l2;
                float w0 = wh_s[cbase], w1 = wh_s[cbase + 1];
                int cu = 4 * u + 64 * j + (lane & 3);
                #pragma unroll
                for (int hf = 0; hf < 2; hf++) {
                    int q0 = 2 * hf, q1 = q0 + 1;
                    int row = l4 + 8 * hf;
                    float2 hv = *(const float2*)(hs + row * HS_STR + cbase);
                    float rv0 = sigf(acc[0][j][q0]), rv1 = sigf(acc[0][j][q1]);
                    float zv0 = sigf(acc[1][j][q0]), zv1 = sigf(acc[1][j][q1]);
                    float nv0 = tanhff(accg[j][q0] + rv0 * acc[2][j][q0]);
                    float nv1 = tanhff(accg[j][q1] + rv1 * acc[2][j][q1]);
                    float h0 = nv0 + zv0 * (hv.x - nv0);
                    float h1 = nv1 + zv1 * (hv.y - nv1);
                    *(float2*)(hs + row * HS_STR + cbase) = make_float2(h0, h1);
                    ps[hf] += h0 * w0 + h1 * w1;
                    AhW[row * A_U32 + cu] = cvt2h(h0, h1);
                }
            }
            #pragma unroll
            for (int hf = 0; hf < 2; hf++) {
                ps[hf] += __shfl_xor_sync(0xffffffffu, ps[hf], 1);
                ps[hf] += __shfl_xor_sync(0xffffffffu, ps[hf], 2);
            }
            if ((lane & 3) == 0) {
                part[l4 * PSTR + u]       = ps[0];
                part[(l4 + 8) * PSTR + u] = ps[1];
            }
        }
        __syncthreads();   // part visible

        // ===== phase 3: base reduce + logits; write fp16 A plane for prev =====
        {
            float pv = (lane < 16) ? part[u * PSTR + lane] : 0.f;
            #pragma unroll
            for (int o = 16; o >= 1; o >>= 1)
                pv += __shfl_xor_sync(0xffffffffu, pv, o);
            float base = pv + b0;

            float wbv = (float)tgt * wb_s[lane];
            float v = wbv;
            #pragma unroll
            for (int o = 1; o < 32; o <<= 1) {
                float uu = __shfl_up_sync(0xffffffffu, v, o);
                if (lane >= o) v += uu;
            }
            float logit = base + (v - wbv);
            out[idx] = logit;
            float pl = __shfl_down_sync(0xffffffffu, logit, 1);
            if (!(lane & 1))
                AhW[u * A_U32 + 128 + (lane >> 1)] = cvt2h(logit, pl);
        }
        __syncthreads();   // A write plane complete before next GEMM
    }
}

extern "C" void kernel_launch(void* const* d_in, const int* in_sizes, int n_in,
                              void* d_out, int out_size)
{
    prep_kernel<<<(NKT * NNT * 32 + 255) / 256, 256>>>(
        (const float*)d_in[8], (const float*)d_in[6]);

    cudaFuncSetAttribute(gru_kernel, cudaFuncAttributeMaxDynamicSharedMemorySize, SMEM_BYTES);
    gru_kernel<<<4096 / BT, NTHR, SMEM_BYTES>>>(
        (const float*)d_in[0], (const int*)d_in[1],
        (const float*)d_in[2], (const float*)d_in[3],
        (const float*)d_in[4], (const float*)d_in[5],
        (const float*)d_in[6], (const float*)d_in[7],
        (const float*)d_in[8], (const float*)d_in[9],
        (const float*)d_in[10], (const float*)d_in[11],
        (float*)d_out);
}

// round 17
// speedup vs baseline: 1.5924x; 1.5924x over previous
#include <cuda_runtime.h>
#include <cuda_fp16.h>

#define NTHR   1024
#define BT     32
#define HDIM   256
#define EDIM   32
#define TSTEPS 64
#define G3     768
#define KB     8
#define NKT    18
#define NNT    96

#define HS_STR 260
#define A_PITCH 296            // fp16 elems per A row
#define A_U32   148            // u32 per A row
#define PSTR    36

// smem offsets (floats)
#define OFF_AH    0            // 4736
#define OFF_HS    4736         // 8320 (persistent h state)
#define OFF_WS    13056        // 2080 (encoder scratch)
#define OFF_XA    15136        // 8320 (encoder scratch)
#define OFF_BSUM  23456        // 768
#define OFF_BHH   24224        // 768
#define OFF_BIH   24992        // 768
#define OFF_WH    25760        // 256
#define OFF_WB    26016        // 32
#define OFF_PART  26048        // 1152
#define OFF_BE1   27200        // 256
#define OFF_BE2   27456        // 256
#define SMEM_FLOATS 27712
#define SMEM_BYTES  (SMEM_FLOATS * 4)   // 110848 bytes

// fp16 W fragments: per (tk,tn,lane): {b0,b1} fp16x2
__device__ uint2 g_wfrag[NKT * NNT * 32];

__device__ __forceinline__ unsigned long long pack2(float x) {
    unsigned long long r; asm("mov.b64 %0, {%1,%1};" : "=l"(r) : "f"(x)); return r;
}
__device__ __forceinline__ void fma2(unsigned long long& d, unsigned long long a, unsigned long long b) {
    asm("fma.rn.f32x2 %0, %1, %2, %0;" : "+l"(d) : "l"(a), "l"(b));
}
__device__ __forceinline__ float2 up2(unsigned long long v) {
    float2 f; asm("mov.b64 {%0,%1}, %2;" : "=f"(f.x), "=f"(f.y) : "l"(v)); return f;
}
// fast gate functions: __fdividef = single rcp.approx (err ~1e-7, << 4e-4 budget)
__device__ __forceinline__ float sigf(float x)  { return __fdividef(1.0f, 1.0f + __expf(-x)); }
__device__ __forceinline__ float tanhff(float x){ return 1.0f - __fdividef(2.0f, __expf(2.0f * x) + 1.0f); }

__device__ __forceinline__ void mma_f16(float* c, const unsigned* a, unsigned b0, unsigned b1) {
    asm("mma.sync.aligned.m16n8k16.row.col.f32.f16.f16.f32 "
        "{%0,%1,%2,%3},{%4,%5,%6,%7},{%8,%9},{%0,%1,%2,%3};"
        : "+f"(c[0]), "+f"(c[1]), "+f"(c[2]), "+f"(c[3])
        : "r"(a[0]), "r"(a[1]), "r"(a[2]), "r"(a[3]), "r"(b0), "r"(b1));
}
__device__ __forceinline__ void ldmat_x4(unsigned* r, unsigned addr) {
    asm volatile("ldmatrix.sync.aligned.m8n8.x4.shared.b16 {%0,%1,%2,%3}, [%4];"
        : "=r"(r[0]), "=r"(r[1]), "=r"(r[2]), "=r"(r[3]) : "r"(addr));
}
// single-instruction pack: lo = a, hi = b  (cvt.rn.f16x2.f32 d, hi_src, lo_src)
__device__ __forceinline__ unsigned cvt2h(float a, float b) {
    unsigned r;
    asm("cvt.rn.f16x2.f32 %0, %1, %2;" : "=r"(r) : "f"(b), "f"(a));
    return r;
}

// ---------- prep: fp16 B-fragments of Wcat = [Whh | Wih] ----------
__global__ void prep_kernel(const float* __restrict__ Whh, const float* __restrict__ Wih) {
    int idx = blockIdx.x * blockDim.x + threadIdx.x;
    if (idx >= NKT * NNT * 32) return;
    int l    = idx & 31;
    int tile = idx >> 5;
    int tn   = tile % NNT;
    int tk   = tile / NNT;
    int n    = tn * 8 + (l >> 2);
    int kb   = tk * 16 + (l & 3) * 2;

    float v[4];
    #pragma unroll
    for (int q = 0; q < 4; q++) {
        int k = kb + (q & 1) + (q >> 1) * 8;
        v[q] = (k < HDIM) ? Whh[n * HDIM + k] : Wih[n * EDIM + (k - HDIM)];
    }
    uint2 o;
    o.x = cvt2h(v[0], v[1]);
    o.y = cvt2h(v[2], v[3]);
    g_wfrag[idx] = o;
}

// ---------- encoder stage (fp32, runs once; 1024 threads) ----------
__device__ __forceinline__ void encoder_stage(
    const float* __restrict__ in, int instr,
    const float* __restrict__ Wg, const float* __restrict__ bias_s,
    float* __restrict__ outp, float* __restrict__ ws)
{
    const int tid = threadIdx.x;
    const int c0 = (tid & 63) * 4;
    const int r0 = (tid >> 6) * 2;
    unsigned long long acc[2][2];
    {
        unsigned long long bp0 = *(const unsigned long long*)(bias_s + c0);
        unsigned long long bp1 = *(const unsigned long long*)(bias_s + c0 + 2);
        #pragma unroll
        for (int r = 0; r < 2; r++) { acc[r][0] = bp0; acc[r][1] = bp1; }
    }
    for (int kc = 0; kc < HDIM / KB; kc++) {
        __syncthreads();
        for (int i = tid; i < KB * HDIM; i += NTHR) {
            int j = i >> 3, k = i & 7;
            ws[k * 260 + j] = Wg[j * HDIM + kc * KB + k];
        }
        __syncthreads();
        #pragma unroll
        for (int k = 0; k < KB; k++) {
            ulonglong2 w = *(const ulonglong2*)(ws + k * 260 + c0);
            #pragma unroll
            for (int r = 0; r < 2; r++) {
                unsigned long long a = pack2(in[(r0 + r) * instr + kc * KB + k]);
                fma2(acc[r][0], a, w.x);
                fma2(acc[r][1], a, w.y);
            }
        }
    }
    __syncthreads();
    #pragma unroll
    for (int r = 0; r < 2; r++) {
        float2 v0 = up2(acc[r][0]);
        float2 v1 = up2(acc[r][1]);
        float* o = outp + (r0 + r) * HS_STR + c0;
        o[0] = fmaxf(v0.x, 0.f); o[1] = fmaxf(v0.y, 0.f);
        o[2] = fmaxf(v1.x, 0.f); o[3] = fmaxf(v1.y, 0.f);
    }
}

extern __shared__ float smem[];

__global__ void __launch_bounds__(NTHR, 1)
gru_kernel(const float* __restrict__ x,   const int*   __restrict__ targets,
           const float* __restrict__ We1, const float* __restrict__ be1,
           const float* __restrict__ We2, const float* __restrict__ be2,
           const float* __restrict__ Wih, const float* __restrict__ bih,
           const float* __restrict__ Whh, const float* __restrict__ bhh,
           const float* __restrict__ Wdec,const float* __restrict__ bdec,
           float* __restrict__ out)
{
    unsigned* Ah32 = (unsigned*)(smem + OFF_AH);
    float* hs     = smem + OFF_HS;
    float* ws     = smem + OFF_WS;
    float* xa     = smem + OFF_XA;
    float* bsum_s = smem + OFF_BSUM;
    float* bhh_s  = smem + OFF_BHH;
    float* bih_s  = smem + OFF_BIH;
    float* wh_s   = smem + OFF_WH;
    float* wb_s   = smem + OFF_WB;
    float* part   = smem + OFF_PART;
    float* be1_s  = smem + OFF_BE1;
    float* be2_s  = smem + OFF_BE2;

    const int tid  = threadIdx.x;
    const int row0 = blockIdx.x * BT;
    const int wid  = tid >> 5;
    const int lane = tid & 31;

    for (int i = tid; i < G3; i += NTHR) {
        float a = bhh[i], b = bih[i];
        bhh_s[i] = a; bih_s[i] = b; bsum_s[i] = a + b;
    }
    for (int i = tid; i < HDIM; i += NTHR) {
        wh_s[i] = Wdec[i]; be1_s[i] = be1[i]; be2_s[i] = be2[i];
    }
    if (tid < EDIM) wb_s[tid] = Wdec[HDIM + tid];
    const float b0 = bdec[0];

    // encoder: x -> xa (stride 260) -> hs (persistent)
    for (int i = tid; i < BT * HDIM; i += NTHR) {
        int r = i >> 8, c = i & 255;
        xa[r * 260 + c] = x[(row0 + r) * HDIM + c];
    }
    __syncthreads();
    encoder_stage(xa, 260, We1, be1_s, hs, ws);
    encoder_stage(hs, HS_STR, We2, be2_s, hs, ws);
    __syncthreads();

    // initial A plane: h0 fp16, prev = 0, pads = 0
    for (int i = tid; i < BT * A_U32; i += NTHR) {
        int r = i / A_U32, cu = i - r * A_U32;
        unsigned hi = 0;
        if (cu < 128) hi = cvt2h(hs[r * HS_STR + 2 * cu], hs[r * HS_STR + 2 * cu + 1]);
        Ah32[r * A_U32 + cu] = hi;
    }
    __syncthreads();

    const int l4 = lane >> 2;
    const int l2 = (lane & 3) * 2;
    const unsigned aoff = (unsigned)((lane & 15) * A_PITCH + (lane >> 4) * 8) * 2u;
    const unsigned ahi_base = (unsigned)__cvta_generic_to_shared(Ah32) + aoff;

    const int out_base = (row0 + wid) * TSTEPS * EDIM + lane;

    for (int t = 0; t < TSTEPS; t++) {
        // prefetch targets for phase 3 (consumed after two barriers)
        const int idx = out_base + t * EDIM;
        const int tgt = targets[idx];

        // ===== GEMM: gates = [h|prev] @ Wcat^T + biases (1-pass fp16) =====
        float acc[3][2][4];
        float accg[2][4];
        {
            #pragma unroll
            for (int i = 0; i < 3; i++) {
                int n0 = (wid + 32 * i) * 8 + l2;
                float v0 = (i < 2) ? bsum_s[n0]     : bhh_s[n0];
                float v1 = (i < 2) ? bsum_s[n0 + 1] : bhh_s[n0 + 1];
                #pragma unroll
                for (int m = 0; m < 2; m++) {
                    acc[i][m][0] = v0; acc[i][m][1] = v1;
                    acc[i][m][2] = v0; acc[i][m][3] = v1;
                }
            }
            {
                int n0 = (wid + 64) * 8 + l2;
                float v0 = bih_s[n0], v1 = bih_s[n0 + 1];
                #pragma unroll
                for (int m = 0; m < 2; m++) {
                    accg[m][0] = v0; accg[m][1] = v1;
                    accg[m][2] = v0; accg[m][3] = v1;
                }
            }
            #pragma unroll 4
            for (int tk = 0; tk < 16; tk++) {
                unsigned ah[2][4];
                #pragma unroll
                for (int m = 0; m < 2; m++)
                    ldmat_x4(ah[m], ahi_base + (unsigned)(m * 16 * A_PITCH + tk * 16) * 2u);
                #pragma unroll
                for (int i = 0; i < 3; i++) {
                    uint2 b = g_wfrag[(tk * NNT + wid + 32 * i) * 32 + lane];
                    #pragma unroll
                    for (int m = 0; m < 2; m++)
                        mma_f16(acc[i][m], ah[m], b.x, b.y);
                }
            }
            #pragma unroll
            for (int tt = 0; tt < 2; tt++) {
                int tk = 16 + tt;
                unsigned ah[2][4];
                #pragma unroll
                for (int m = 0; m < 2; m++)
                    ldmat_x4(ah[m], ahi_base + (unsigned)(m * 16 * A_PITCH + tk * 16) * 2u);
                #pragma unroll
                for (int i = 0; i < 3; i++) {
                    uint2 b = g_wfrag[(tk * NNT + wid + 32 * i) * 32 + lane];
                    #pragma unroll
                    for (int m = 0; m < 2; m++) {
                        float* T = (i < 2) ? acc[i][m] : accg[m];
                        mma_f16(T, ah[m], b.x, b.y);
                    }
                }
            }
        }
        __syncthreads();

        // ===== phase 2: gates, h update (smem), A-plane write, psum =====
        {
            const int cbase = 8 * wid + l2;
            const float w0 = wh_s[cbase], w1 = wh_s[cbase + 1];
            const int cu = 4 * wid + (lane & 3);
            float ps[4];
            #pragma unroll
            for (int m = 0; m < 2; m++) {
                #pragma unroll
                for (int hf = 0; hf < 2; hf++) {
                    int g = 2 * m + hf, q0 = 2 * hf, q1 = q0 + 1;
                    int row = 8 * g + l4;
                    float2 hv = *(const float2*)(hs + row * HS_STR + cbase);
                    float rv0 = sigf(acc[0][m][q0]), rv1 = sigf(acc[0][m][q1]);
                    float zv0 = sigf(acc[1][m][q0]), zv1 = sigf(acc[1][m][q1]);
                    float nv0 = tanhff(accg[m][q0] + rv0 * acc[2][m][q0]);
                    float nv1 = tanhff(accg[m][q1] + rv1 * acc[2][m][q1]);
                    float h0 = nv0 + zv0 * (hv.x - nv0);
                    float h1 = nv1 + zv1 * (hv.y - nv1);
                    *(float2*)(hs + row * HS_STR + cbase) = make_float2(h0, h1);
                    ps[g] = h0 * w0 + h1 * w1;
                    Ah32[row * A_U32 + cu] = cvt2h(h0, h1);
                }
            }
            #pragma unroll
            for (int g = 0; g < 4; g++) {
                ps[g] += __shfl_xor_sync(0xffffffffu, ps[g], 1);
                ps[g] += __shfl_xor_sync(0xffffffffu, ps[g], 2);
            }
            if ((lane & 3) == 0) {
                #pragma unroll
                for (int g = 0; g < 4; g++)
                    part[(8 * g + l4) * PSTR + wid] = ps[g];
            }
        }
        __syncthreads();

        // ===== phase 3: base reduce + logits; write fp16 A plane for prev =====
        {
            int row = wid;
            float pv = part[row * PSTR + lane];
            #pragma unroll
            for (int o = 16; o >= 1; o >>= 1)
                pv += __shfl_xor_sync(0xffffffffu, pv, o);
            float base = pv + b0;

            float wbv = (float)tgt * wb_s[lane];
            float v = wbv;
            #pragma unroll
            for (int o = 1; o < 32; o <<= 1) {
                float u = __shfl_up_sync(0xffffffffu, v, o);
                if (lane >= o) v += u;
            }
            float logit = base + (v - wbv);
            out[idx] = logit;
            float pl = __shfl_down_sync(0xffffffffu, logit, 1);
            if (!(lane & 1))
                Ah32[row * A_U32 + 128 + (lane >> 1)] = cvt2h(logit, pl);
        }
        __syncthreads();
    }
}

extern "C" void kernel_launch(void* const* d_in, const int* in_sizes, int n_in,
                              void* d_out, int out_size)
{
    prep_kernel<<<(NKT * NNT * 32 + 255) / 256, 256>>>(
        (const float*)d_in[8], (const float*)d_in[6]);

    cudaFuncSetAttribute(gru_kernel, cudaFuncAttributeMaxDynamicSharedMemorySize, SMEM_BYTES);
    gru_kernel<<<4096 / BT, NTHR, SMEM_BYTES>>>(
        (const float*)d_in[0], (const int*)d_in[1],
        (const float*)d_in[2], (const float*)d_in[3],
        (const float*)d_in[4], (const float*)d_in[5],
        (const float*)d_in[6], (const float*)d_in[7],
        (const float*)d_in[8], (const float*)d_in[9],
        (const float*)d_in[10], (const float*)d_in[11],
        (float*)d_out);
}